// round 5
// baseline (speedup 1.0000x reference)
#include <cuda_runtime.h>

#define DIM 256
#define BATCH 32768
#define NW 26

typedef unsigned long long ull;

// ---- packed f32x2 helpers (PTX-only path on sm_103a) ----
__device__ __forceinline__ ull pk2(float lo, float hi) {
    ull r; asm("mov.b64 %0, {%1,%2};" : "=l"(r) : "f"(lo), "f"(hi)); return r;
}
__device__ __forceinline__ float lo2(ull v) {
    float a, b; asm("mov.b64 {%0,%1}, %2;" : "=f"(a), "=f"(b) : "l"(v)); return a;
}
__device__ __forceinline__ float hi2(ull v) {
    float a, b; asm("mov.b64 {%0,%1}, %2;" : "=f"(a), "=f"(b) : "l"(v)); return b;
}
__device__ __forceinline__ ull mul2(ull a, ull b) {
    ull d; asm("mul.rn.f32x2 %0, %1, %2;" : "=l"(d) : "l"(a), "l"(b)); return d;
}
__device__ __forceinline__ ull add2(ull a, ull b) {
    ull d; asm("add.rn.f32x2 %0, %1, %2;" : "=l"(d) : "l"(a), "l"(b)); return d;
}
__device__ __forceinline__ ull fma2(ull a, ull b, ull c) {
    ull d; asm("fma.rn.f32x2 %0, %1, %2, %3;" : "=l"(d) : "l"(a), "l"(b), "l"(c)); return d;
}
__device__ __forceinline__ ull swap2(ull v) {  // (lo,hi) -> (hi,lo)
    ull d;
    asm("{\n\t.reg .b32 a,b;\n\tmov.b64 {a,b}, %1;\n\tmov.b64 %0, {b,a};\n\t}"
        : "=l"(d) : "l"(v));
    return d;
}

// tan-form rotation, in-register axis (reg mask M): a'=a-t*b, b'=b+t*a
template<int M>
__device__ __forceinline__ void rot_reg(ull* u, float t) {
    ull tp = pk2(t, t), tn = pk2(-t, -t);
    #pragma unroll
    for (int k = 0; k < 16; k++) {
        if (k & M) continue;
        ull a = u[k];
        u[k]     = fma2(tn, u[k | M], a);
        u[k | M] = fma2(tp, a, u[k | M]);
    }
}
// tan-form rotation, cross-lane axis (lane mask LM)
template<int LM>
__device__ __forceinline__ void rot_cross(ull* u, float t, int lane) {
    float se = (lane & LM) ? t : -t;
    ull sev = pk2(se, se);
    #pragma unroll
    for (int k = 0; k < 16; k++) {
        ull pv = __shfl_xor_sync(0xffffffffu, u[k], LM);
        u[k] = fma2(sev, pv, u[k]);
    }
}
// tan-form rotation, pack axis: lo' = lo - t*hi, hi' = hi + t*lo
__device__ __forceinline__ void rot_pack(ull* u, float t) {
    ull ts = pk2(-t, t);
    #pragma unroll
    for (int k = 0; k < 16; k++)
        u[k] = fma2(ts, swap2(u[k]), u[k]);
}

// Bit layout (index i, 8 bits; wire w <-> bit (7-w)):
//   reg bits  k[3:0] = {i7,i6,i5,i4}  -> wires 0,1,2,3 (masks 8,4,2,1)
//   lane bits jl = i[3:1]             -> wires 4,5,6   (shfl masks 4,2,1)
//   pack bit  i[0]                    -> wire 7        (f32x2 lo/hi)
// Warp = 4 samples (g = lane>>3), lane holds 32 amps as 16 ull. State real.
// RY in tan-form (uniform cos dropped; normalize by final state norm).
__global__ __launch_bounds__(128, 6) void qae_kernel(const float* __restrict__ x,
                                                     const float* __restrict__ w,
                                                     float* __restrict__ out) {
    __shared__ float st[NW];
    int tid = threadIdx.x;
    if (tid < NW) {
        float s, c;
        sincosf(0.5f * w[tid], &s, &c);
        st[tid] = s / c;                         // tan(theta/2)
    }
    __syncthreads();

    int lane = tid & 31;
    int jl = lane & 7;
    int g = lane >> 3;
    int warp = (blockIdx.x * blockDim.x + tid) >> 5;
    int smp = warp * 4 + g;

    // amp i = k*16 + jl*2 + pack  ->  float2 #(k*8 + jl) of the sample row
    ull u[16];
    {
        const float2* p = reinterpret_cast<const float2*>(x + (size_t)smp * DIM) + jl;
        #pragma unroll
        for (int k = 0; k < 16; k++) {
            float2 v = p[k * 8];
            u[k] = pk2(v.x, v.y);
        }
    }

    // CZ parity(i) = (b0&b1) ^ ((b0^b1) & popc(i[5:0])&1), b0=i7=k3, b1=i6=k2.
    // popc(i[5:0])&1 = (k1^k0) ^ popc(jl) ^ i0.  Per-thread runtime part: jp.
    const ull SIGN_BOTH = 0x8000000080000000ull;
    const ull SIGN_LO   = 0x0000000080000000ull;
    const ull SIGN_HI   = 0x8000000000000000ull;
    int jp = __popc(jl) & 1;
    ull mx0 = jp ? SIGN_LO : SIGN_HI;   // b0^b1=1 classes, kp = k1^k0 = 0
    ull mx1 = jp ? SIGN_HI : SIGN_LO;   // kp = 1

    #pragma unroll
    for (int l = 0; l < 3; l++) {
        const int b = l * 8;
        // all 8 RYs of a layer commute: interleave cross-lane (MIO) with reg (FMA)
        rot_cross<4>(u, st[b + 4], lane);
        rot_reg<8>(u, st[b + 0]);
        rot_cross<2>(u, st[b + 5], lane);
        rot_reg<4>(u, st[b + 1]);
        rot_cross<1>(u, st[b + 6], lane);
        rot_reg<2>(u, st[b + 2]);
        rot_pack(u, st[b + 7]);
        rot_reg<1>(u, st[b + 3]);
        // fused CZ: k3=k2=0 -> no-op; k3=k2=1 -> flip both; k3^k2=1 -> flip one half
        #pragma unroll
        for (int k = 4; k < 12; k++) {
            const int kp = ((k >> 1) ^ k) & 1;
            u[k] ^= kp ? mx1 : mx0;
        }
        #pragma unroll
        for (int k = 12; k < 16; k++) u[k] ^= SIGN_BOTH;
    }

    // final layer: trash wires 0,1 -> in-register masks 8,4
    rot_reg<8>(u, st[24]);
    rot_reg<4>(u, st[25]);

    // ---- expectations: wire6 = lane bit0, wire7 = pack bit ----
    // Full-index sums (each bra index i counted once), normalized by 1/n2.
    // YY sign = -(-1)^(i1+i0).
    ull SG = (lane & 1) ? pk2(1.0f, -1.0f) : pk2(-1.0f, 1.0f);
    ull X6 = 0, X7 = 0, XX = 0, YY = 0, Qp = 0;
    #pragma unroll
    for (int k = 0; k < 16; k++) {
        ull v = u[k];
        ull pv = __shfl_xor_sync(0xffffffffu, v, 1);  // flip i1 (wire 6)
        X6 = fma2(v, pv, X6);
        ull sv = swap2(pv);                           // flip i1 and i0
        ull prod = mul2(v, sv);
        XX = add2(XX, prod);
        YY = fma2(SG, prod, YY);
        X7 = fma2(v, swap2(v), X7);                   // flip i0 (wire 7)
        Qp = fma2(v, v, Qp);
    }
    ull Qs = Qp ^ ((lane & 1) ? SIGN_BOTH : 0ull);    // (-1)^{i1} weights (exact)
    #pragma unroll
    for (int m = 4; m; m >>= 1) {
        X6 = add2(X6, __shfl_xor_sync(0xffffffffu, X6, m));
        X7 = add2(X7, __shfl_xor_sync(0xffffffffu, X7, m));
        XX = add2(XX, __shfl_xor_sync(0xffffffffu, XX, m));
        YY = add2(YY, __shfl_xor_sync(0xffffffffu, YY, m));
        Qp = add2(Qp, __shfl_xor_sync(0xffffffffu, Qp, m));
        Qs = add2(Qs, __shfl_xor_sync(0xffffffffu, Qs, m));
    }

    if (jl == 0) {
        float n2  = lo2(Qp) + hi2(Qp);                // final-state norm^2
        float sz7 = lo2(Qp) - hi2(Qp);                // sum (-1)^{i0} psi^2
        float sz6 = lo2(Qs) + hi2(Qs);                // sum (-1)^{i1} psi^2
        float szz = lo2(Qs) - hi2(Qs);                // sum (-1)^{i1+i0} psi^2
        float inv = 1.0f / n2;
        float* o = out + (size_t)smp * 9;
        o[0] = (lo2(X6) + hi2(X6)) * inv;
        o[1] = 0.0f;                                  // <Y> on a real state = 0
        o[2] = sz6 * inv;
        o[3] = (lo2(X7) + hi2(X7)) * inv;
        o[4] = 0.0f;
        o[5] = sz7 * inv;
        o[6] = (lo2(XX) + hi2(XX)) * inv;
        o[7] = (lo2(YY) + hi2(YY)) * inv;
        o[8] = szz * inv;
    }
}

extern "C" void kernel_launch(void* const* d_in, const int* in_sizes, int n_in,
                              void* d_out, int out_size) {
    const float* x = (const float*)d_in[0];
    const float* w = (const float*)d_in[1];
    if (n_in >= 2 && in_sizes[0] == NW) { const float* t = x; x = w; w = t; }
    float* out = (float*)d_out;
    // 128 threads = 4 warps = 16 samples per block
    qae_kernel<<<BATCH / 16, 128>>>(x, w, out);
}

// round 7
// speedup vs baseline: 1.1235x; 1.1235x over previous
#include <cuda_runtime.h>

#define DIM 256
#define BATCH 32768
#define NW 26

typedef unsigned long long ull;

// ---- packed f32x2 helpers (PTX-only path on sm_103a) ----
__device__ __forceinline__ ull pk2(float lo, float hi) {
    ull r; asm("mov.b64 %0, {%1,%2};" : "=l"(r) : "f"(lo), "f"(hi)); return r;
}
__device__ __forceinline__ float lo2(ull v) {
    float a, b; asm("mov.b64 {%0,%1}, %2;" : "=f"(a), "=f"(b) : "l"(v)); return a;
}
__device__ __forceinline__ float hi2(ull v) {
    float a, b; asm("mov.b64 {%0,%1}, %2;" : "=f"(a), "=f"(b) : "l"(v)); return b;
}
__device__ __forceinline__ ull fma2(ull a, ull b, ull c) {
    ull d; asm("fma.rn.f32x2 %0, %1, %2, %3;" : "=l"(d) : "l"(a), "l"(b), "l"(c)); return d;
}

// tan-form rotation, in-register axis (reg mask M): a'=a-t*b, b'=b+t*a
template<int M>
__device__ __forceinline__ void rot_reg(ull* u, float t) {
    ull tp = pk2(t, t), tn = pk2(-t, -t);
    #pragma unroll
    for (int k = 0; k < 32; k++) {
        if (k & M) continue;
        ull a = u[k];
        u[k]     = fma2(tn, u[k | M], a);
        u[k | M] = fma2(tp, a, u[k | M]);
    }
}
// tan-form rotation, cross-lane axis (lane mask LM)
template<int LM>
__device__ __forceinline__ void rot_cross(ull* u, float t, int lane) {
    float se = (lane & LM) ? t : -t;
    ull sev = pk2(se, se);
    #pragma unroll
    for (int k = 0; k < 32; k++) {
        ull pv = __shfl_xor_sync(0xffffffffu, u[k], LM);
        u[k] = fma2(sev, pv, u[k]);
    }
}
// tan-form rotation on the pack axis, scalar halves (no swap MOVs):
// lo' = lo - t*hi, hi' = hi + t*lo
__device__ __forceinline__ void rot_pack(ull* u, float t) {
    #pragma unroll
    for (int k = 0; k < 32; k++) {
        float lo = lo2(u[k]), hi = hi2(u[k]);
        float nl = fmaf(-t, hi, lo);
        float nh = fmaf( t, lo, hi);
        u[k] = pk2(nl, nh);
    }
}

// Bit layout (index i, 8 bits; wire w <-> bit (7-w)):
//   reg bits  k[4:0] = {i7,i6,i5,i4,i1} -> wires 0,1,2,3 (masks 16,8,4,2), wire 6 (mask 1)
//   lane bits i[3:2] = j                -> wires 4,5 (shfl masks 2,1)
//   pack bit  i[0]                      -> wire 7 (f32x2 lo/hi)
// Warp = 8 samples (g = lane>>2), lane holds 64 amps as 32 ull. State real.
// RY in tan-form (uniform cos dropped; normalize by final state norm).
__global__ __launch_bounds__(128, 5) void qae_kernel(const float* __restrict__ x,
                                                     const float* __restrict__ w,
                                                     float* __restrict__ out) {
    __shared__ float st[NW];
    int tid = threadIdx.x;
    if (tid < NW) {
        float s, c;
        sincosf(0.5f * w[tid], &s, &c);
        st[tid] = s / c;                         // tan(theta/2)
    }
    __syncthreads();

    int lane = tid & 31;
    int j = lane & 3;
    int g = lane >> 2;
    int warp = (blockIdx.x * blockDim.x + tid) >> 5;
    int smp = warp * 8 + g;

    // Load: float4 #f at amp i = f*16 + j*4 -> u[2f] = (c0,c1), u[2f+1] = (c2,c3)
    ull u[32];
    {
        const float4* p = reinterpret_cast<const float4*>(x + (size_t)smp * DIM);
        #pragma unroll
        for (int f = 0; f < 16; f++) {
            float4 v = p[f * 4 + j];
            u[2 * f]     = pk2(v.x, v.y);
            u[2 * f + 1] = pk2(v.z, v.w);
        }
    }

    // CZ parity(i) = (b0&b1) ^ ((b0^b1) & popc(i[5:0])&1), b0=i7=k4, b1=i6=k3.
    // popc(i[5:0])&1 = (k2^k1^k0) ^ parity(j) ^ i0(pack).
    const ull SIGN_BOTH = 0x8000000080000000ull;
    const ull SIGN_LO   = 0x0000000080000000ull;
    const ull SIGN_HI   = 0x8000000000000000ull;
    int jp = (j ^ (j >> 1)) & 1;
    ull mx0 = jp ? SIGN_LO : SIGN_HI;   // b0^b1=1 classes, rp = k2^k1^k0 = 0
    ull mx1 = jp ? SIGN_HI : SIGN_LO;   // rp = 1

    #pragma unroll
    for (int l = 0; l < 3; l++) {
        const int b = l * 8;
        // all 8 RYs of a layer commute: interleave cross-lane (MIO) with reg (FMA)
        rot_cross<2>(u, st[b + 4], lane);   // wire 4
        rot_reg<16>(u, st[b + 0]);          // wire 0
        rot_cross<1>(u, st[b + 5], lane);   // wire 5
        rot_reg<8>(u, st[b + 1]);           // wire 1
        rot_pack(u, st[b + 7]);             // wire 7 (scalar halves)
        rot_reg<4>(u, st[b + 2]);           // wire 2
        rot_reg<2>(u, st[b + 3]);           // wire 3
        rot_reg<1>(u, st[b + 6]);           // wire 6
        // fused CZ: k4=k3=0 -> no-op; k4=k3=1 -> flip both halves; k4^k3=1 -> one half
        #pragma unroll
        for (int k = 8; k < 24; k++) {
            const int rp = ((k >> 2) ^ (k >> 1) ^ k) & 1;
            u[k] ^= rp ? mx1 : mx0;
        }
        #pragma unroll
        for (int k = 24; k < 32; k++) u[k] ^= SIGN_BOTH;
    }

    // final layer: trash wires 0,1 -> in-register masks 16, 8
    rot_reg<16>(u, st[24]);
    rot_reg<8>(u, st[25]);

    // ---- expectations: wire6 = k bit0, wire7 = pack bit ----
    // Half-set sums (each unordered pair once; x2 in epilogue).
    ull X6 = 0, QE = 0, QO = 0;
    float x7 = 0.f, xx = 0.f, yy = 0.f;
    #pragma unroll
    for (int s = 0; s < 16; s++) {
        ull a = u[2 * s], b = u[2 * s + 1];          // a: i1=0, b: i1=1
        X6 = fma2(a, b, X6);                         // pairs (i, i^2)
        float al = lo2(a), ah = hi2(a), bl = lo2(b), bh = hi2(b);
        x7 = fmaf(al, ah, x7);                       // pairs (i, i^1)
        x7 = fmaf(bl, bh, x7);
        xx = fmaf(al, bh, xx);                       // pairs (i, i^3)
        xx = fmaf(ah, bl, xx);
        yy = fmaf(ah, bl, yy);                       // {01,10}: +, {00,11}: -
        yy = fmaf(-al, bh, yy);
        QE = fma2(a, a, QE);                         // lo->cls00, hi->cls01
        QO = fma2(b, b, QO);                         // lo->cls10, hi->cls11
    }
    // reduce within the 4-lane sample group (masks 2,1)
    #pragma unroll
    for (int m = 2; m; m >>= 1) {
        X6 = fma2(pk2(1.f, 1.f), __shfl_xor_sync(0xffffffffu, X6, m), X6);
        QE = fma2(pk2(1.f, 1.f), __shfl_xor_sync(0xffffffffu, QE, m), QE);
        QO = fma2(pk2(1.f, 1.f), __shfl_xor_sync(0xffffffffu, QO, m), QO);
        x7 += __shfl_xor_sync(0xffffffffu, x7, m);
        xx += __shfl_xor_sync(0xffffffffu, xx, m);
        yy += __shfl_xor_sync(0xffffffffu, yy, m);
    }

    if (j == 0) {
        float q0 = lo2(QE), q1 = hi2(QE), q2 = lo2(QO), q3 = hi2(QO);
        float n2 = (q0 + q1) + (q2 + q3);            // final-state norm^2
        float inv  = 1.0f / n2;
        float inv2 = inv + inv;
        float* o = out + (size_t)smp * 9;
        o[0] = (lo2(X6) + hi2(X6)) * inv2;           // <X> wire 6
        o[1] = 0.0f;                                 // <Y> on a real state = 0
        o[2] = ((q0 + q1) - (q2 + q3)) * inv;        // <Z> wire 6
        o[3] = x7 * inv2;                            // <X> wire 7
        o[4] = 0.0f;
        o[5] = ((q0 + q2) - (q1 + q3)) * inv;        // <Z> wire 7
        o[6] = xx * inv2;                            // <XX>
        o[7] = yy * inv2;                            // <YY>
        o[8] = ((q0 + q3) - (q1 + q2)) * inv;        // <ZZ>
    }
}

extern "C" void kernel_launch(void* const* d_in, const int* in_sizes, int n_in,
                              void* d_out, int out_size) {
    const float* x = (const float*)d_in[0];
    const float* w = (const float*)d_in[1];
    if (n_in >= 2 && in_sizes[0] == NW) { const float* t = x; x = w; w = t; }
    float* out = (float*)d_out;
    // 128 threads = 4 warps = 32 samples per block
    qae_kernel<<<BATCH / 32, 128>>>(x, w, out);
}